// round 3
// baseline (speedup 1.0000x reference)
#include <cuda_runtime.h>

#define B_    8
#define CDIM  512
#define NH    8
#define HD    64
#define NT    1024   // 32*32 tokens

// Scratch for Q/K/V in [b, head, n, d] layout (16.8 MB each)
__device__ float g_q[B_ * NH * NT * HD];
__device__ float g_k[B_ * NH * NT * HD];
__device__ float g_v[B_ * NH * NT * HD];

// ---------------------------------------------------------------------------
// QKV projection: per batch b, T[n, dcol] = sum_c x[b,c,n] * W[c,dcol] + bias
// Block computes a 64(n) x 64(d) tile; tile d-range == exactly one head.
// grid = (NT/64, NH, B_), block = (16,16), each thread 4x4 outputs.
// ---------------------------------------------------------------------------
__global__ __launch_bounds__(256) void proj_kernel(
    const float* __restrict__ x,
    const float* __restrict__ w,
    const float* __restrict__ bias,
    int which)
{
    __shared__ float As[16][64];   // x chunk: [c][n]
    __shared__ float Bs[16][64];   // w chunk: [c][d]

    const int tx = threadIdx.x, ty = threadIdx.y;
    const int t  = ty * 16 + tx;
    const int n0 = blockIdx.x * 64;
    const int head = blockIdx.y;
    const int d0 = head * 64;
    const int b  = blockIdx.z;

    const int lk = t >> 4;          // 0..15 : c-row within chunk
    const int lc = (t & 15) * 4;    // 0..60 : col (float4)

    const float* xb = x + (size_t)b * CDIM * NT + n0;

    float acc[4][4];
    #pragma unroll
    for (int j = 0; j < 4; j++) {
        float bj = bias[d0 + tx * 4 + j];
        #pragma unroll
        for (int i = 0; i < 4; i++) acc[i][j] = bj;
    }

    for (int c0 = 0; c0 < CDIM; c0 += 16) {
        float4 av = *(const float4*)(xb + (size_t)(c0 + lk) * NT + lc);
        float4 wv = *(const float4*)(w + (size_t)(c0 + lk) * CDIM + d0 + lc);
        *(float4*)&As[lk][lc] = av;
        *(float4*)&Bs[lk][lc] = wv;
        __syncthreads();
        #pragma unroll
        for (int kk = 0; kk < 16; kk++) {
            float4 a  = *(const float4*)&As[kk][ty * 4];
            float4 bb = *(const float4*)&Bs[kk][tx * 4];
            float ar[4] = {a.x, a.y, a.z, a.w};
            float br[4] = {bb.x, bb.y, bb.z, bb.w};
            #pragma unroll
            for (int i = 0; i < 4; i++)
                #pragma unroll
                for (int j = 0; j < 4; j++)
                    acc[i][j] += ar[i] * br[j];
        }
        __syncthreads();
    }

    float* dst = (which == 0) ? g_q : (which == 1) ? g_k : g_v;
    float* op = dst + ((size_t)(b * NH + head) * NT + n0) * HD;
    #pragma unroll
    for (int i = 0; i < 4; i++) {
        float4 v;
        v.x = acc[i][0]; v.y = acc[i][1]; v.z = acc[i][2]; v.w = acc[i][3];
        *(float4*)&op[(ty * 4 + i) * HD + tx * 4] = v;
    }
}

// ---------------------------------------------------------------------------
// Flash attention, fp32, online softmax.
// grid = (NT/64 query tiles, NH, B_), block = (16,16).
// smem: Qs[64*64] | Ks[64*65] (also holds P, also output-transpose) | Vs[64*64]
// ---------------------------------------------------------------------------
__global__ __launch_bounds__(256) void attn_kernel(float* __restrict__ out)
{
    extern __shared__ float sm[];
    float* Qs = sm;                 // 4096 floats, stride 64
    float* Ks = sm + 64 * 64;       // 4160 floats, stride 65 (K tile / P tile / transpose)
    float* Vs = Ks + 64 * 65;       // 4096 floats, stride 64

    const int tx = threadIdx.x, ty = threadIdx.y;
    const int t  = ty * 16 + tx;
    const int n0 = blockIdx.x * 64;
    const int h  = blockIdx.y;
    const int b  = blockIdx.z;

    const size_t bh = (size_t)(b * NH + h) * NT * HD;
    const float* qg = g_q + bh + (size_t)n0 * HD;
    const float* kg = g_k + bh;
    const float* vg = g_v + bh;

    // Q tile is 4096 contiguous floats
    #pragma unroll
    for (int r = 0; r < 4; r++) {
        int e = (r * 256 + t) * 4;
        *(float4*)&Qs[e] = *(const float4*)&qg[e];
    }

    float o[4][4];
    #pragma unroll
    for (int i = 0; i < 4; i++)
        #pragma unroll
        for (int j = 0; j < 4; j++) o[i][j] = 0.f;
    float m_i[4], l_i[4];
    #pragma unroll
    for (int i = 0; i < 4; i++) { m_i[i] = -1e30f; l_i[i] = 0.f; }

    for (int kt = 0; kt < 16; kt++) {
        __syncthreads();   // previous iteration's PV reads of Ks/Vs done
        const float* kp = kg + kt * 64 * HD;
        const float* vp = vg + kt * 64 * HD;
        #pragma unroll
        for (int r = 0; r < 4; r++) {
            int e = (r * 256 + t) * 4;
            int row = e >> 6, col = e & 63;
            float4 kv = *(const float4*)&kp[e];
            Ks[row * 65 + col + 0] = kv.x;
            Ks[row * 65 + col + 1] = kv.y;
            Ks[row * 65 + col + 2] = kv.z;
            Ks[row * 65 + col + 3] = kv.w;
            *(float4*)&Vs[e] = *(const float4*)&vp[e];
        }
        __syncthreads();

        // S = Q K^T for this 64x64 tile; thread owns rows 4ty+i, keys 4tx+j
        float s[4][4];
        #pragma unroll
        for (int i = 0; i < 4; i++)
            #pragma unroll
            for (int j = 0; j < 4; j++) s[i][j] = 0.f;
        #pragma unroll 8
        for (int kk = 0; kk < 64; kk++) {
            float a[4], bb[4];
            #pragma unroll
            for (int i = 0; i < 4; i++) a[i]  = Qs[(ty * 4 + i) * 64 + kk];
            #pragma unroll
            for (int j = 0; j < 4; j++) bb[j] = Ks[(tx * 4 + j) * 65 + kk];
            #pragma unroll
            for (int i = 0; i < 4; i++)
                #pragma unroll
                for (int j = 0; j < 4; j++)
                    s[i][j] += a[i] * bb[j];
        }

        // online softmax update (row groups = 16 lanes sharing ty)
        float sc[4];
        #pragma unroll
        for (int i = 0; i < 4; i++) {
            float mt = fmaxf(fmaxf(s[i][0], s[i][1]), fmaxf(s[i][2], s[i][3]));
            mt = fmaxf(mt, __shfl_xor_sync(0xffffffffu, mt, 1));
            mt = fmaxf(mt, __shfl_xor_sync(0xffffffffu, mt, 2));
            mt = fmaxf(mt, __shfl_xor_sync(0xffffffffu, mt, 4));
            mt = fmaxf(mt, __shfl_xor_sync(0xffffffffu, mt, 8));
            float mnew = fmaxf(m_i[i], mt);
            sc[i] = __expf(m_i[i] - mnew);
            m_i[i] = mnew;
            float rs = 0.f;
            #pragma unroll
            for (int j = 0; j < 4; j++) {
                s[i][j] = __expf(s[i][j] - mnew);
                rs += s[i][j];
            }
            rs += __shfl_xor_sync(0xffffffffu, rs, 1);
            rs += __shfl_xor_sync(0xffffffffu, rs, 2);
            rs += __shfl_xor_sync(0xffffffffu, rs, 4);
            rs += __shfl_xor_sync(0xffffffffu, rs, 8);
            l_i[i] = l_i[i] * sc[i] + rs;
            #pragma unroll
            for (int j = 0; j < 4; j++) o[i][j] *= sc[i];
        }

        __syncthreads();   // everyone done reading Ks (K data) before overwrite with P
        #pragma unroll
        for (int i = 0; i < 4; i++)
            #pragma unroll
            for (int j = 0; j < 4; j++)
                Ks[(ty * 4 + i) * 65 + tx * 4 + j] = s[i][j];
        __syncthreads();

        // O += P V ; thread owns rows 4ty+i, out-dims 4tx+j
        #pragma unroll 8
        for (int kk = 0; kk < 64; kk++) {
            float p[4];
            #pragma unroll
            for (int i = 0; i < 4; i++) p[i] = Ks[(ty * 4 + i) * 65 + kk];
            float4 vv = *(const float4*)&Vs[kk * 64 + tx * 4];
            float vr[4] = {vv.x, vv.y, vv.z, vv.w};
            #pragma unroll
            for (int i = 0; i < 4; i++)
                #pragma unroll
                for (int j = 0; j < 4; j++)
                    o[i][j] += p[i] * vr[j];
        }
    }

    // normalize
    #pragma unroll
    for (int i = 0; i < 4; i++) {
        float inv = 1.f / l_i[i];
        #pragma unroll
        for (int j = 0; j < 4; j++) o[i][j] *= inv;
    }

    // transpose through smem so d-major gmem writes coalesce over n
    __syncthreads();
    #pragma unroll
    for (int i = 0; i < 4; i++)
        #pragma unroll
        for (int j = 0; j < 4; j++)
            Ks[(tx * 4 + j) * 65 + ty * 4 + i] = o[i][j];
    __syncthreads();

    float* og = out + ((size_t)b * CDIM + h * HD) * NT + n0;
    #pragma unroll
    for (int r = 0; r < 4; r++) {
        int e = (r * 256 + t) * 4;
        int d = e >> 6, n = e & 63;
        float4 v;
        v.x = Ks[d * 65 + n + 0];
        v.y = Ks[d * 65 + n + 1];
        v.z = Ks[d * 65 + n + 2];
        v.w = Ks[d * 65 + n + 3];
        *(float4*)&og[(size_t)d * NT + n] = v;
    }
}

// ---------------------------------------------------------------------------
extern "C" void kernel_launch(void* const* d_in, const int* in_sizes, int n_in,
                              void* d_out, int out_size)
{
    const float* x  = (const float*)d_in[0];
    const float* wq = (const float*)d_in[1];
    const float* bq = (const float*)d_in[2];
    const float* wk = (const float*)d_in[3];
    const float* bk = (const float*)d_in[4];
    const float* wv = (const float*)d_in[5];
    const float* bv = (const float*)d_in[6];
    float* out = (float*)d_out;

    dim3 blk(16, 16);
    dim3 gproj(NT / 64, NH, B_);
    proj_kernel<<<gproj, blk>>>(x, wq, bq, 0);
    proj_kernel<<<gproj, blk>>>(x, wk, bk, 1);
    proj_kernel<<<gproj, blk>>>(x, wv, bv, 2);

    const int smem = (64 * 64 + 64 * 65 + 64 * 64) * sizeof(float); // 49408 B
    cudaFuncSetAttribute(attn_kernel,
                         cudaFuncAttributeMaxDynamicSharedMemorySize, smem);
    attn_kernel<<<dim3(NT / 64, NH, B_), blk, smem>>>(out);
}